// round 8
// baseline (speedup 1.0000x reference)
#include <cuda_runtime.h>
#include <cuda_bf16.h>
#include <cstdint>

#define NN 100000
#define EE 1250000
#define DD 64
#define NB ((NN + 255) / 256)   // 391 scan blocks
#define NPB 16                  // nodes per fused block

// ---------------------------------------------------------------------------
// Scratch (__device__ globals; zero-initialized at load; self-restoring)
// ---------------------------------------------------------------------------
__device__ int   g_cnt[NN];                // edge count per dst (cleared by scan1)
__device__ float g_dis[NN];                // deg^{-1/2}
__device__ int   g_rowptr[NN];             // local-exclusive after scan1; local-inclusive after reorder
__device__ int   g_bsum[NB];               // block totals (scan1)
__device__ int   g_bsumx[NB];              // exclusive block offsets (scan2)
__device__ int2  g_epair[EE];              // (src, w-bits), dst-grouped
__device__ float g_h[NN * DD];             // gemm1 output
__device__ float g_h2[NN * DD];            // fused gather1+gemm2 output

// ---------------------------------------------------------------------------
// Histogram: int count, 4 edges/thread.
// ---------------------------------------------------------------------------
__global__ void k_hist(const int* __restrict__ dst) {
    int t = blockIdx.x * blockDim.x + threadIdx.x;
    int e = t * 4;
    if (e + 4 <= EE) {
        int4 d = *reinterpret_cast<const int4*>(dst + e);
        atomicAdd(&g_cnt[d.x], 1);
        atomicAdd(&g_cnt[d.y], 1);
        atomicAdd(&g_cnt[d.z], 1);
        atomicAdd(&g_cnt[d.w], 1);
    } else {
        for (; e < EE; e++) atomicAdd(&g_cnt[dst[e]], 1);
    }
}

// ---------------------------------------------------------------------------
// scan1: read+clear cnt, block-local exclusive scan.
// ---------------------------------------------------------------------------
__global__ void k_scan1() {
    __shared__ int sh[256];
    int t = threadIdx.x;
    int i = blockIdx.x * 256 + t;
    int cnt = 0;
    if (i < NN) {
        cnt = g_cnt[i];
        g_cnt[i] = 0;                                  // restore for next run
    }
    sh[t] = cnt;
    __syncthreads();
    for (int off = 1; off < 256; off <<= 1) {
        int u = (t >= off) ? sh[t - off] : 0;
        __syncthreads();
        sh[t] += u;
        __syncthreads();
    }
    if (i < NN) g_rowptr[i] = sh[t] - cnt;             // local exclusive
    if (t == 255) g_bsum[blockIdx.x] = sh[255];
}

// scan2: exclusive scan of 391 block totals -> g_bsumx
__global__ void k_scan2() {
    __shared__ int sh[512];
    int t = threadIdx.x;
    int v = (t < NB) ? g_bsum[t] : 0;
    sh[t] = v;
    __syncthreads();
    for (int off = 1; off < 512; off <<= 1) {
        int u = (t >= off) ? sh[t - off] : 0;
        __syncthreads();
        sh[t] += u;
        __syncthreads();
    }
    if (t < NB) g_bsumx[t] = sh[t] - v;
}

// ---------------------------------------------------------------------------
// Reorder: place (src, w-bits), 4 edges/thread vectorized.
// ---------------------------------------------------------------------------
__global__ void k_reorder(const int* __restrict__ src, const int* __restrict__ dst,
                          const float* __restrict__ w) {
    int t = blockIdx.x * blockDim.x + threadIdx.x;
    int e = t * 4;
    if (e + 4 <= EE) {
        int4 s = *reinterpret_cast<const int4*>(src + e);
        int4 d = *reinterpret_cast<const int4*>(dst + e);
        float4 wv = *reinterpret_cast<const float4*>(w + e);
        int p0 = g_bsumx[d.x >> 8] + atomicAdd(&g_rowptr[d.x], 1);
        int p1 = g_bsumx[d.y >> 8] + atomicAdd(&g_rowptr[d.y], 1);
        int p2 = g_bsumx[d.z >> 8] + atomicAdd(&g_rowptr[d.z], 1);
        int p3 = g_bsumx[d.w >> 8] + atomicAdd(&g_rowptr[d.w], 1);
        g_epair[p0] = make_int2(s.x, __float_as_int(wv.x));
        g_epair[p1] = make_int2(s.y, __float_as_int(wv.y));
        g_epair[p2] = make_int2(s.z, __float_as_int(wv.z));
        g_epair[p3] = make_int2(s.w, __float_as_int(wv.w));
    } else {
        for (; e < EE; e++) {
            int d = dst[e];
            int pos = g_bsumx[d >> 8] + atomicAdd(&g_rowptr[d], 1);
            g_epair[pos] = make_int2(src[e], __float_as_int(w[e]));
        }
    }
}

// ---------------------------------------------------------------------------
// Weighted degree by CSR row-sum -> dis. One warp/node, no atomics.
// ---------------------------------------------------------------------------
__global__ void k_deg() {
    int n = (blockIdx.x * blockDim.x + threadIdx.x) >> 5;
    if (n >= NN) return;
    int lane = threadIdx.x & 31;
    int beg = (n == 0) ? 0 : (g_rowptr[n - 1] + g_bsumx[(n - 1) >> 8]);
    int end = g_rowptr[n] + g_bsumx[n >> 8];
    float s = 0.0f;
    for (int j = beg + lane; j < end; j += 32)
        s += __int_as_float(g_epair[j].y);
#pragma unroll
    for (int off = 16; off > 0; off >>= 1)
        s += __shfl_xor_sync(0xffffffffu, s, off);
    if (lane == 0) g_dis[n] = rsqrtf(s + 1.0f);
}

// ---------------------------------------------------------------------------
// Register-blocked GEMM (layer 1): H[n][o] = sum_k X[n][k] * W[o][k]
// ---------------------------------------------------------------------------
__global__ void __launch_bounds__(256) k_gemm(const float* __restrict__ X,
                                              const float* __restrict__ W,
                                              float* __restrict__ H) {
    __shared__ float Xs[128][65];
    __shared__ float Ws[DD][DD];      // Ws[k][o] = W[o][k]

    int tid = threadIdx.x;
    int lane = tid & 31;
    int grp  = tid >> 5;
    int row0 = blockIdx.x * 128;

    for (int idx = tid; idx < (DD * DD) / 4; idx += 256) {
        int o = idx >> 4;
        int k4 = (idx & 15) * 4;
        float4 v = *reinterpret_cast<const float4*>(W + o * DD + k4);
        Ws[k4 + 0][o] = v.x;
        Ws[k4 + 1][o] = v.y;
        Ws[k4 + 2][o] = v.z;
        Ws[k4 + 3][o] = v.w;
    }
    for (int idx = tid; idx < (128 * DD) / 4; idx += 256) {
        int r = idx >> 4;
        int k4 = (idx & 15) * 4;
        int row = row0 + r;
        float4 v = (row < NN) ? *reinterpret_cast<const float4*>(X + (size_t)row * DD + k4)
                              : make_float4(0.f, 0.f, 0.f, 0.f);
        Xs[r][k4 + 0] = v.x;
        Xs[r][k4 + 1] = v.y;
        Xs[r][k4 + 2] = v.z;
        Xs[r][k4 + 3] = v.w;
    }
    __syncthreads();

    int c0 = grp * 8;
    float acc[4][8];
#pragma unroll
    for (int i = 0; i < 4; i++)
#pragma unroll
        for (int j = 0; j < 8; j++) acc[i][j] = 0.0f;

#pragma unroll 4
    for (int k = 0; k < DD; k++) {
        float xv0 = Xs[lane      ][k];
        float xv1 = Xs[lane + 32 ][k];
        float xv2 = Xs[lane + 64 ][k];
        float xv3 = Xs[lane + 96 ][k];
        float4 w0 = *reinterpret_cast<const float4*>(&Ws[k][c0]);
        float4 w1 = *reinterpret_cast<const float4*>(&Ws[k][c0 + 4]);
        float wv[8] = {w0.x, w0.y, w0.z, w0.w, w1.x, w1.y, w1.z, w1.w};
#pragma unroll
        for (int j = 0; j < 8; j++) {
            acc[0][j] = fmaf(xv0, wv[j], acc[0][j]);
            acc[1][j] = fmaf(xv1, wv[j], acc[1][j]);
            acc[2][j] = fmaf(xv2, wv[j], acc[2][j]);
            acc[3][j] = fmaf(xv3, wv[j], acc[3][j]);
        }
    }

#pragma unroll
    for (int i = 0; i < 4; i++) {
        int row = row0 + lane + i * 32;
        if (row < NN) {
            float* hp = H + (size_t)row * DD + c0;
            *reinterpret_cast<float4*>(hp)     = make_float4(acc[i][0], acc[i][1], acc[i][2], acc[i][3]);
            *reinterpret_cast<float4*>(hp + 4) = make_float4(acc[i][4], acc[i][5], acc[i][6], acc[i][7]);
        }
    }
}

// ---------------------------------------------------------------------------
// Warp-level CSR row gather: returns lane's float2 accum (coef inline).
// ---------------------------------------------------------------------------
__device__ __forceinline__ float2 gather_row(int n, int lane,
                                             const float2* __restrict__ H2v) {
    int beg = (n == 0) ? 0 : (g_rowptr[n - 1] + g_bsumx[(n - 1) >> 8]);
    int end = g_rowptr[n] + g_bsumx[n >> 8];
    float dn = g_dis[n];

    float2 a0 = make_float2(0.f, 0.f), a1 = a0, a2 = a0, a3 = a0;

    int2 p[8];
#pragma unroll
    for (int j = 0; j < 8; j++)
        p[j] = (beg + j < end) ? g_epair[beg + j] : make_int2(0, 0);

    int e = beg;
    while (e + 8 <= end) {
        float ds[8];
        float2 f[8];
#pragma unroll
        for (int j = 0; j < 8; j++) {
            ds[j] = g_dis[p[j].x];
            f[j] = H2v[((size_t)p[j].x << 5) + lane];
        }
        int2 np[8];
#pragma unroll
        for (int j = 0; j < 8; j++)
            np[j] = (e + 8 + j < end) ? g_epair[e + 8 + j] : make_int2(0, 0);

#pragma unroll
        for (int j = 0; j < 8; j++) {
            float c = ds[j] * __int_as_float(p[j].y) * dn;
            float2* a = (j & 3) == 0 ? &a0 : (j & 3) == 1 ? &a1 : (j & 3) == 2 ? &a2 : &a3;
            a->x = fmaf(c, f[j].x, a->x);
            a->y = fmaf(c, f[j].y, a->y);
        }
#pragma unroll
        for (int j = 0; j < 8; j++) p[j] = np[j];
        e += 8;
    }

    int rem = end - e;
#pragma unroll
    for (int j = 0; j < 8; j++) {
        if (j < rem) {
            float c = g_dis[p[j].x] * __int_as_float(p[j].y) * dn;
            float2 f = H2v[((size_t)p[j].x << 5) + lane];
            float2* a = (j & 3) == 0 ? &a0 : (j & 3) == 1 ? &a1 : (j & 3) == 2 ? &a2 : &a3;
            a->x = fmaf(c, f.x, a->x);
            a->y = fmaf(c, f.y, a->y);
        }
    }

    float s2 = dn * dn;
    float2 hs = H2v[((size_t)n << 5) + lane];
    float2 r;
    r.x = (a0.x + a1.x) + (a2.x + a3.x) + hs.x * s2;
    r.y = (a0.y + a1.y) + (a2.y + a3.y) + hs.y * s2;
    return r;
}

// ---------------------------------------------------------------------------
// FUSED: gather layer1 (+bias,relu) into smem, then 16x64 GEMM with W2.
// 256 threads, 8 warps; each warp gathers 2 nodes.
// ---------------------------------------------------------------------------
__global__ void __launch_bounds__(256) k_gather_gemm(const float* __restrict__ H,
                                                     const float* __restrict__ W2,
                                                     const float* __restrict__ b1,
                                                     float* __restrict__ H2) {
    __shared__ float sA[NPB][66];     // relu(agg+b1), pad 66 (8B-aligned rows)
    __shared__ float sW[DD][DD];      // sW[k][o] = W2[o][k]

    int tid = threadIdx.x;
    int warp = tid >> 5;
    int lane = tid & 31;
    int node0 = blockIdx.x * NPB;
    const float2* __restrict__ Hv = reinterpret_cast<const float2*>(H);

    // stage W2 transposed
    for (int idx = tid; idx < (DD * DD) / 4; idx += 256) {
        int o = idx >> 4;
        int k4 = (idx & 15) * 4;
        float4 v = *reinterpret_cast<const float4*>(W2 + o * DD + k4);
        sW[k4 + 0][o] = v.x;
        sW[k4 + 1][o] = v.y;
        sW[k4 + 2][o] = v.z;
        sW[k4 + 3][o] = v.w;
    }

    // gather phase: 8 warps x 2 nodes
    float2 bv = reinterpret_cast<const float2*>(b1)[lane];
#pragma unroll
    for (int i = 0; i < 2; i++) {
        int local = warp * 2 + i;
        int n = node0 + local;
        if (n < NN) {
            float2 r = gather_row(n, lane, Hv);
            r.x = fmaxf(r.x + bv.x, 0.0f);
            r.y = fmaxf(r.y + bv.y, 0.0f);
            sA[local][lane * 2]     = r.x;
            sA[local][lane * 2 + 1] = r.y;
        }
    }
    __syncthreads();

    // gemm phase: thread = 1 row x 4 cols
    int row = tid >> 4;               // 0..15
    int cq = (tid & 15) * 4;
    int n = node0 + row;
    if (n >= NN) return;

    float4 acc = make_float4(0.f, 0.f, 0.f, 0.f);
#pragma unroll 8
    for (int k = 0; k < DD; k++) {
        float a = sA[row][k];
        float4 wv = *reinterpret_cast<const float4*>(&sW[k][cq]);
        acc.x = fmaf(a, wv.x, acc.x);
        acc.y = fmaf(a, wv.y, acc.y);
        acc.z = fmaf(a, wv.z, acc.z);
        acc.w = fmaf(a, wv.w, acc.w);
    }
    *reinterpret_cast<float4*>(H2 + (size_t)n * DD + cq) = acc;
}

// ---------------------------------------------------------------------------
// Final gather (layer 2): out = gather(H2) + b2, no relu.
// ---------------------------------------------------------------------------
__global__ void k_gather2(const float* __restrict__ H, float* __restrict__ OUT,
                          const float* __restrict__ b) {
    int n = (blockIdx.x * blockDim.x + threadIdx.x) >> 5;
    if (n >= NN) return;
    int lane = threadIdx.x & 31;
    const float2* __restrict__ Hv = reinterpret_cast<const float2*>(H);

    float2 r = gather_row(n, lane, Hv);
    float2 bv = reinterpret_cast<const float2*>(b)[lane];
    r.x += bv.x;
    r.y += bv.y;
    reinterpret_cast<float2*>(OUT)[((size_t)n << 5) + lane] = r;
}

// ---------------------------------------------------------------------------
// Launch (k_reorder at position #4 -> profiled by ncu)
// ---------------------------------------------------------------------------
extern "C" void kernel_launch(void* const* d_in, const int* in_sizes, int n_in,
                              void* d_out, int out_size) {
    const float* x  = (const float*)d_in[0];
    const int*   ei = (const int*)d_in[1];
    const float* w  = (const float*)d_in[2];
    const float* W1 = (const float*)d_in[3];
    const float* b1 = (const float*)d_in[4];
    const float* W2 = (const float*)d_in[5];
    const float* b2 = (const float*)d_in[6];
    float* out = (float*)d_out;

    const int* src = ei;
    const int* dst = ei + EE;

    float* h_p;   cudaGetSymbolAddress((void**)&h_p,   g_h);
    float* h2_p;  cudaGetSymbolAddress((void**)&h2_p,  g_h2);

    const int T = 256;
    int bE4 = (EE / 4 + T - 1) / T;            // 1221
    int bG  = (NN + 127) / 128;                // 782
    int bW  = (NN * 32 + T - 1) / T;           // 12500 (1 warp/node)
    int bF  = (NN + NPB - 1) / NPB;            // 6250 fused blocks

    k_hist<<<bE4, T>>>(dst);                   // #1
    k_scan1<<<NB, 256>>>();                    // #2
    k_scan2<<<1, 512>>>();                     // #3
    k_reorder<<<bE4, T>>>(src, dst, w);        // #4  <-- profiled
    k_deg<<<bW, T>>>();                        // #5
    k_gemm<<<bG, T>>>(x, W1, h_p);             // #6
    k_gather_gemm<<<bF, T>>>(h_p, W2, b1, h2_p); // #7 fused gather1 + gemm2
    k_gather2<<<bW, T>>>(h2_p, out, b2);       // #8
}

// round 9
// speedup vs baseline: 1.2520x; 1.2520x over previous
#include <cuda_runtime.h>
#include <cuda_bf16.h>
#include <cstdint>

#define NN 100000
#define EE 1250000
#define DD 64
#define NB ((NN + 255) / 256)   // 391 scan blocks

// ---------------------------------------------------------------------------
// Scratch (__device__ globals; zero-initialized at load; self-restoring)
// ---------------------------------------------------------------------------
__device__ int   g_cnt[NN];                // edge count per dst (cleared by scan1)
__device__ float g_deg[NN];                // weighted degree (cleared by scan1)
__device__ float g_dis[NN];                // deg^{-1/2}
__device__ int   g_rowptr[NN];             // local-exclusive after scan1; local-inclusive after reorder
__device__ int   g_bsum[NB];               // block totals (scan1)
__device__ int   g_bsumx[NB];              // exclusive block offsets (scan2)
__device__ int2  g_epair[EE];              // (src, coef-bits), dst-grouped
__device__ float g_h[NN * DD];             // gemm output buffer
__device__ float g_agg[NN * DD];           // gather output buffer

// ---------------------------------------------------------------------------
// Histogram: int count + float weighted degree, 4 edges/thread.
// ---------------------------------------------------------------------------
__global__ void k_hist(const int* __restrict__ dst, const float* __restrict__ w) {
    int t = blockIdx.x * blockDim.x + threadIdx.x;
    int e = t * 4;
    if (e + 4 <= EE) {
        int4 d = *reinterpret_cast<const int4*>(dst + e);
        float4 wv = *reinterpret_cast<const float4*>(w + e);
        atomicAdd(&g_cnt[d.x], 1);
        atomicAdd(&g_cnt[d.y], 1);
        atomicAdd(&g_cnt[d.z], 1);
        atomicAdd(&g_cnt[d.w], 1);
        atomicAdd(&g_deg[d.x], wv.x);
        atomicAdd(&g_deg[d.y], wv.y);
        atomicAdd(&g_deg[d.z], wv.z);
        atomicAdd(&g_deg[d.w], wv.w);
    } else {
        for (; e < EE; e++) {
            atomicAdd(&g_cnt[dst[e]], 1);
            atomicAdd(&g_deg[dst[e]], w[e]);
        }
    }
}

// ---------------------------------------------------------------------------
// scan1: read+clear cnt/deg, compute dis, block-local exclusive scan.
// ---------------------------------------------------------------------------
__global__ void k_scan1() {
    __shared__ int sh[256];
    int t = threadIdx.x;
    int i = blockIdx.x * 256 + t;
    int cnt = 0;
    if (i < NN) {
        cnt = g_cnt[i];
        g_cnt[i] = 0;                                  // restore for next run
        float deg = g_deg[i];
        g_deg[i] = 0.0f;                               // restore for next run
        g_dis[i] = rsqrtf(deg + 1.0f);
    }
    sh[t] = cnt;
    __syncthreads();
    for (int off = 1; off < 256; off <<= 1) {
        int u = (t >= off) ? sh[t - off] : 0;
        __syncthreads();
        sh[t] += u;
        __syncthreads();
    }
    if (i < NN) g_rowptr[i] = sh[t] - cnt;             // local exclusive
    if (t == 255) g_bsum[blockIdx.x] = sh[255];
}

// scan2: exclusive scan of 391 block totals -> g_bsumx
__global__ void k_scan2() {
    __shared__ int sh[512];
    int t = threadIdx.x;
    int v = (t < NB) ? g_bsum[t] : 0;
    sh[t] = v;
    __syncthreads();
    for (int off = 1; off < 512; off <<= 1) {
        int u = (t >= off) ? sh[t - off] : 0;
        __syncthreads();
        sh[t] += u;
        __syncthreads();
    }
    if (t < NB) g_bsumx[t] = sh[t] - v;
}

// ---------------------------------------------------------------------------
// Reorder: place (src, coef-bits), coef = dis[s]*w*dis[d]. 4 edges/thread.
// ---------------------------------------------------------------------------
__global__ void k_reorder(const int* __restrict__ src, const int* __restrict__ dst,
                          const float* __restrict__ w) {
    int t = blockIdx.x * blockDim.x + threadIdx.x;
    int e = t * 4;
    if (e + 4 <= EE) {
        int4 s = *reinterpret_cast<const int4*>(src + e);
        int4 d = *reinterpret_cast<const int4*>(dst + e);
        float4 wv = *reinterpret_cast<const float4*>(w + e);
        float c0 = g_dis[s.x] * wv.x * g_dis[d.x];
        float c1 = g_dis[s.y] * wv.y * g_dis[d.y];
        float c2 = g_dis[s.z] * wv.z * g_dis[d.z];
        float c3 = g_dis[s.w] * wv.w * g_dis[d.w];
        int p0 = g_bsumx[d.x >> 8] + atomicAdd(&g_rowptr[d.x], 1);
        int p1 = g_bsumx[d.y >> 8] + atomicAdd(&g_rowptr[d.y], 1);
        int p2 = g_bsumx[d.z >> 8] + atomicAdd(&g_rowptr[d.z], 1);
        int p3 = g_bsumx[d.w >> 8] + atomicAdd(&g_rowptr[d.w], 1);
        g_epair[p0] = make_int2(s.x, __float_as_int(c0));
        g_epair[p1] = make_int2(s.y, __float_as_int(c1));
        g_epair[p2] = make_int2(s.z, __float_as_int(c2));
        g_epair[p3] = make_int2(s.w, __float_as_int(c3));
    } else {
        for (; e < EE; e++) {
            int sv = src[e];
            int d = dst[e];
            float c = g_dis[sv] * w[e] * g_dis[d];
            int pos = g_bsumx[d >> 8] + atomicAdd(&g_rowptr[d], 1);
            g_epair[pos] = make_int2(sv, __float_as_int(c));
        }
    }
}

// ---------------------------------------------------------------------------
// Register-blocked GEMM: H[n][o] = sum_k X[n][k] * W[o][k]
// 256 threads, 128x64 tile, 4x8 outputs/thread. k-step-4 float4 LDS reads.
// Xs pad 68: row stride 68 ≡ 4 (mod 32 banks) -> conflict-free LDS.128 phases.
// ---------------------------------------------------------------------------
__global__ void __launch_bounds__(256) k_gemm(const float* __restrict__ X,
                                              const float* __restrict__ W,
                                              float* __restrict__ H) {
    __shared__ float Xs[128][68];
    __shared__ float Ws[DD][DD];      // Ws[k][o] = W[o][k]

    int tid = threadIdx.x;
    int lane = tid & 31;
    int grp  = tid >> 5;
    int row0 = blockIdx.x * 128;

    for (int idx = tid; idx < (DD * DD) / 4; idx += 256) {
        int o = idx >> 4;
        int k4 = (idx & 15) * 4;
        float4 v = *reinterpret_cast<const float4*>(W + o * DD + k4);
        Ws[k4 + 0][o] = v.x;
        Ws[k4 + 1][o] = v.y;
        Ws[k4 + 2][o] = v.z;
        Ws[k4 + 3][o] = v.w;
    }
    for (int idx = tid; idx < (128 * DD) / 4; idx += 256) {
        int r = idx >> 4;
        int k4 = (idx & 15) * 4;
        int row = row0 + r;
        float4 v = (row < NN) ? *reinterpret_cast<const float4*>(X + (size_t)row * DD + k4)
                              : make_float4(0.f, 0.f, 0.f, 0.f);
        *reinterpret_cast<float4*>(&Xs[r][k4]) = v;
    }
    __syncthreads();

    int c0 = grp * 8;
    float acc[4][8];
#pragma unroll
    for (int i = 0; i < 4; i++)
#pragma unroll
        for (int j = 0; j < 8; j++) acc[i][j] = 0.0f;

#pragma unroll
    for (int k = 0; k < DD; k += 4) {
        float4 xv0 = *reinterpret_cast<const float4*>(&Xs[lane      ][k]);
        float4 xv1 = *reinterpret_cast<const float4*>(&Xs[lane + 32 ][k]);
        float4 xv2 = *reinterpret_cast<const float4*>(&Xs[lane + 64 ][k]);
        float4 xv3 = *reinterpret_cast<const float4*>(&Xs[lane + 96 ][k]);
        float x0[4] = {xv0.x, xv0.y, xv0.z, xv0.w};
        float x1[4] = {xv1.x, xv1.y, xv1.z, xv1.w};
        float x2[4] = {xv2.x, xv2.y, xv2.z, xv2.w};
        float x3[4] = {xv3.x, xv3.y, xv3.z, xv3.w};
#pragma unroll
        for (int kk = 0; kk < 4; kk++) {
            float4 w0 = *reinterpret_cast<const float4*>(&Ws[k + kk][c0]);
            float4 w1 = *reinterpret_cast<const float4*>(&Ws[k + kk][c0 + 4]);
            float wv[8] = {w0.x, w0.y, w0.z, w0.w, w1.x, w1.y, w1.z, w1.w};
#pragma unroll
            for (int j = 0; j < 8; j++) {
                acc[0][j] = fmaf(x0[kk], wv[j], acc[0][j]);
                acc[1][j] = fmaf(x1[kk], wv[j], acc[1][j]);
                acc[2][j] = fmaf(x2[kk], wv[j], acc[2][j]);
                acc[3][j] = fmaf(x3[kk], wv[j], acc[3][j]);
            }
        }
    }

#pragma unroll
    for (int i = 0; i < 4; i++) {
        int row = row0 + lane + i * 32;
        if (row < NN) {
            float* hp = H + (size_t)row * DD + c0;
            *reinterpret_cast<float4*>(hp)     = make_float4(acc[i][0], acc[i][1], acc[i][2], acc[i][3]);
            *reinterpret_cast<float4*>(hp + 4) = make_float4(acc[i][4], acc[i][5], acc[i][6], acc[i][7]);
        }
    }
}

// ---------------------------------------------------------------------------
// CSR gather, 1 warp/node, float2/lane, 8-edge prefetched batches.
// epair holds (src, coef-bits). (R7-proven path: 58us)
// ---------------------------------------------------------------------------
__global__ void k_gather(const float* __restrict__ H, float* __restrict__ OUT,
                         const float* __restrict__ b, int do_relu) {
    int n = (blockIdx.x * blockDim.x + threadIdx.x) >> 5;
    if (n >= NN) return;
    int lane = threadIdx.x & 31;
    const float2* __restrict__ H2 = reinterpret_cast<const float2*>(H);

    int beg = (n == 0) ? 0 : (g_rowptr[n - 1] + g_bsumx[(n - 1) >> 8]);
    int end = g_rowptr[n] + g_bsumx[n >> 8];

    float2 a0 = make_float2(0.f, 0.f), a1 = a0, a2 = a0, a3 = a0;

    int2 p[8];
#pragma unroll
    for (int j = 0; j < 8; j++)
        p[j] = (beg + j < end) ? g_epair[beg + j] : make_int2(0, 0);

    int e = beg;
    while (e + 8 <= end) {
        float2 f[8];
#pragma unroll
        for (int j = 0; j < 8; j++)
            f[j] = H2[((size_t)p[j].x << 5) + lane];

        int2 np[8];
#pragma unroll
        for (int j = 0; j < 8; j++)
            np[j] = (e + 8 + j < end) ? g_epair[e + 8 + j] : make_int2(0, 0);

#pragma unroll
        for (int j = 0; j < 8; j++) {
            float c = __int_as_float(p[j].y);
            float2* a = (j & 3) == 0 ? &a0 : (j & 3) == 1 ? &a1 : (j & 3) == 2 ? &a2 : &a3;
            a->x = fmaf(c, f[j].x, a->x);
            a->y = fmaf(c, f[j].y, a->y);
        }
#pragma unroll
        for (int j = 0; j < 8; j++) p[j] = np[j];
        e += 8;
    }

    int rem = end - e;
#pragma unroll
    for (int j = 0; j < 8; j++) {
        if (j < rem) {
            float2 f = H2[((size_t)p[j].x << 5) + lane];
            float c = __int_as_float(p[j].y);
            float2* a = (j & 3) == 0 ? &a0 : (j & 3) == 1 ? &a1 : (j & 3) == 2 ? &a2 : &a3;
            a->x = fmaf(c, f.x, a->x);
            a->y = fmaf(c, f.y, a->y);
        }
    }

    float dn = g_dis[n];
    float s2 = dn * dn;
    float2 hs = H2[((size_t)n << 5) + lane];
    float2 bv = reinterpret_cast<const float2*>(b)[lane];

    float ox = (a0.x + a1.x) + (a2.x + a3.x) + hs.x * s2 + bv.x;
    float oy = (a0.y + a1.y) + (a2.y + a3.y) + hs.y * s2 + bv.y;
    if (do_relu) { ox = fmaxf(ox, 0.f); oy = fmaxf(oy, 0.f); }
    reinterpret_cast<float2*>(OUT)[((size_t)n << 5) + lane] = make_float2(ox, oy);
}

// ---------------------------------------------------------------------------
// Launch (k_gemm at position #4 -> profiled by ncu)
// ---------------------------------------------------------------------------
extern "C" void kernel_launch(void* const* d_in, const int* in_sizes, int n_in,
                              void* d_out, int out_size) {
    const float* x  = (const float*)d_in[0];
    const int*   ei = (const int*)d_in[1];
    const float* w  = (const float*)d_in[2];
    const float* W1 = (const float*)d_in[3];
    const float* b1 = (const float*)d_in[4];
    const float* W2 = (const float*)d_in[5];
    const float* b2 = (const float*)d_in[6];
    float* out = (float*)d_out;

    const int* src = ei;
    const int* dst = ei + EE;

    float* h_p;   cudaGetSymbolAddress((void**)&h_p,   g_h);
    float* agg_p; cudaGetSymbolAddress((void**)&agg_p, g_agg);

    const int T = 256;
    int bE4 = (EE / 4 + T - 1) / T;            // 1221
    int bG  = (NN + 127) / 128;                // 782
    int bW  = (NN * 32 + T - 1) / T;           // 12500 (1 warp/node)

    k_hist<<<bE4, T>>>(dst, w);                // #1 (cnt + weighted deg)
    k_scan1<<<NB, 256>>>();                    // #2 (also dis; clears cnt/deg)
    k_scan2<<<1, 512>>>();                     // #3
    k_gemm<<<bG, T>>>(x, W1, h_p);             // #4  <-- profiled (independent of build)
    k_reorder<<<bE4, T>>>(src, dst, w);        // #5 (coef fused)
    k_gather<<<bW, T>>>(h_p, agg_p, b1, 1);    // #6
    k_gemm<<<bG, T>>>(agg_p, W2, h_p);         // #7
    k_gather<<<bW, T>>>(h_p, out, b2, 0);      // #8
}